// round 17
// baseline (speedup 1.0000x reference)
#include <cuda_runtime.h>
#include <math.h>

// Problem dims
#define SDIM 256
#define BDIM 64
#define EDIM 1024
#define VDIM 5

#define NCTA 256
#define NTHR 256

// ---------------- scratch (device globals; no allocs allowed) ----------------
#define KT_OFF   0
#define VT_OFF   16777216
#define H1_OFF   33554432
#define C1_OFF   33619968
#define H2_OFF   33685504
#define C2_OFF   33751040
#define QP_OFF   33816576              // 4 x 65536 q split-K partials
#define WOP_OFF  34078720              // 4 x 65536 wo split-K partials
#define ATT_OFF  34340864
#define G1_OFF   34406400              // 7 x 262144 gate1 partials (8 reserved)
#define G2_OFF   36503552              // 7 x 262144 gate2 partials (8 reserved)
#define QT_OFF   38600704              // w_q  k-major [1024 x 1024]
#define OT_OFF   39649280              // w_o  k-major [1024 x 1024]
#define G1T_OFF  40697856              // [h2|h1|ctx] k-major [3072 x 4096]
#define G2T_OFF  53280768              // [h1new|h2prev] k-major [2048 x 4096]
#define BUF_TOTAL 61669376

__device__ float g_buf[BUF_TOTAL];
__device__ unsigned g_cnt[16 * 32];    // 16 group counters, 128B apart
__device__ unsigned g_bar_root = 0;
__device__ unsigned g_bar_gen = 0;

// smem: A dup 2 stages x 16x132, W 4 stages x 16x64
#define AD_STAGE 2112
#define WS_STAGE 1024
#define SH_FLOATS (2*AD_STAGE + 4*WS_STAGE)    // 8320 floats = 33.3 KB

// ---------------- helpers ----------------
__device__ __forceinline__ void fma2(unsigned long long &d, unsigned long long a, unsigned long long b) {
    asm("fma.rn.f32x2 %0, %1, %2, %0;" : "+l"(d) : "l"(a), "l"(b));
}
__device__ __forceinline__ float2 upk2(unsigned long long v) {
    float lo, hi;
    asm("mov.b64 {%0,%1}, %2;" : "=f"(lo), "=f"(hi) : "l"(v));
    return make_float2(lo, hi);
}
__device__ __forceinline__ float sigf(float x) { return 1.f / (1.f + expf(-x)); }
__device__ __forceinline__ void cp16(void* dst_smem, const void* src) {
    unsigned d = (unsigned)__cvta_generic_to_shared(dst_smem);
    asm volatile("cp.async.cg.shared.global [%0], [%1], 16;" :: "r"(d), "l"(src));
}
#define CP_COMMIT() asm volatile("cp.async.commit_group;" ::: "memory")
#define CP_WAIT2()  asm volatile("cp.async.wait_group 2;" ::: "memory")

// ---------------- two-level grid barrier (16 groups x 16 CTAs) ----------------
__device__ __forceinline__ void grid_bar(int grp) {
    __threadfence();
    __syncthreads();
    if (threadIdx.x == 0) {
        volatile unsigned* vg = &g_bar_gen;
        unsigned gen = *vg;
        if (atomicAdd(&g_cnt[grp << 5], 1u) == 15u) {     // last in group
            g_cnt[grp << 5] = 0u;
            __threadfence();
            if (atomicAdd(&g_bar_root, 1u) == 15u) {      // last group
                g_bar_root = 0u;
                __threadfence();
                *vg = gen + 1u;
            }
        }
        while (*vg == gen) { __nanosleep(32); }
    }
    __syncthreads();
}

// ---------------- setup: weight transpose to k-major fp32 (ONE launch) ----------------
// G1T rows: [h2: wih1[:, :1024] | h1: whh1 | ctx: wih1[:, 1024:]]
// G2T rows: [h1new: wih2 | h2prev: whh2]
__global__ void prep_weights(const float* __restrict__ wq,   const float* __restrict__ wo,
                             const float* __restrict__ wih1, const float* __restrict__ whh1,
                             const float* __restrict__ wih2, const float* __restrict__ whh2) {
    __shared__ float tile[32][33];
    int b = blockIdx.x;
    const float* src; int lds, dOff, ldd, kdst0, kb, nb;
    if (b < 1024)       { int r2 = b;         src = wq;   lds = 1024; dOff = QT_OFF;  ldd = 1024; kb = r2 & 31; nb = r2 >> 5; kdst0 = 0; }
    else if (b < 2048)  { int r2 = b - 1024;  src = wo;   lds = 1024; dOff = OT_OFF;  ldd = 1024; kb = r2 & 31; nb = r2 >> 5; kdst0 = 0; }
    else if (b < 10240) { int r2 = b - 2048;  src = wih1; lds = 2048; dOff = G1T_OFF; ldd = 4096; kb = r2 & 63; nb = r2 >> 6;
                          kdst0 = (kb < 32) ? 0 : 1024; }   // cols >=1024 (ctx) shift to rows 2048+
    else if (b < 14336) { int r2 = b - 10240; src = whh1; lds = 1024; dOff = G1T_OFF; ldd = 4096; kb = r2 & 31; nb = r2 >> 5; kdst0 = 1024; }
    else if (b < 18432) { int r2 = b - 14336; src = wih2; lds = 1024; dOff = G2T_OFF; ldd = 4096; kb = r2 & 31; nb = r2 >> 5; kdst0 = 0; }
    else                { int r2 = b - 18432; src = whh2; lds = 1024; dOff = G2T_OFF; ldd = 4096; kb = r2 & 31; nb = r2 >> 5; kdst0 = 1024; }
    int k0 = kb << 5, n0 = nb << 5;
    int tx = threadIdx.x, ty = threadIdx.y;   // 32 x 8
#pragma unroll
    for (int j = 0; j < 4; j++)
        tile[ty + j*8][tx] = src[(size_t)(n0 + ty + j*8) * lds + k0 + tx];
    __syncthreads();
    float* dst = g_buf + dOff;
#pragma unroll
    for (int j = 0; j < 4; j++)
        dst[(size_t)(kdst0 + k0 + ty + j*8) * ldd + n0 + tx] = tile[tx][ty + j*8];
}

// ---------------- K/V precompute GEMM (fp32) ----------------
__global__ __launch_bounds__(256) void gemm_kv(const float* __restrict__ cnn,
                                               const float* __restrict__ w_qkv,
                                               const float* __restrict__ b_qkv) {
    __shared__ float As[16 * 68];
    __shared__ float Ws[16 * 68];
    int tid = threadIdx.x;
    int ty = tid >> 4, tx = tid & 15;
    int lr = tid >> 2, lk = (tid & 3) << 2;
    int n0 = blockIdx.x << 6;
    int m0 = blockIdx.y << 6;

    const float* Arow = cnn + (size_t)(m0 + lr) * EDIM + lk;
    const float* Wrow = w_qkv + (size_t)(EDIM + n0 + lr) * EDIM + lk;

    float acc[4][4];
#pragma unroll
    for (int i = 0; i < 4; i++)
#pragma unroll
        for (int j = 0; j < 4; j++) acc[i][j] = 0.f;

    float4 av = *(const float4*)(Arow);
    float4 wv = *(const float4*)(Wrow);
    for (int kt = 0; kt < EDIM; kt += 16) {
        __syncthreads();
        As[(lk)*68+lr]=av.x; As[(lk+1)*68+lr]=av.y; As[(lk+2)*68+lr]=av.z; As[(lk+3)*68+lr]=av.w;
        Ws[(lk)*68+lr]=wv.x; Ws[(lk+1)*68+lr]=wv.y; Ws[(lk+2)*68+lr]=wv.z; Ws[(lk+3)*68+lr]=wv.w;
        __syncthreads();
        if (kt + 16 < EDIM) {
            av = *(const float4*)(Arow + kt + 16);
            wv = *(const float4*)(Wrow + kt + 16);
        }
#pragma unroll
        for (int k = 0; k < 16; k++) {
            float4 a = *(const float4*)&As[k*68 + (ty<<2)];
            float4 w = *(const float4*)&Ws[k*68 + (tx<<2)];
            float ar[4] = {a.x, a.y, a.z, a.w};
            float wr[4] = {w.x, w.y, w.z, w.w};
#pragma unroll
            for (int i = 0; i < 4; i++)
#pragma unroll
                for (int j = 0; j < 4; j++) acc[i][j] = fmaf(ar[i], wr[j], acc[i][j]);
        }
    }
#pragma unroll
    for (int i = 0; i < 4; i++) {
        int mg = m0 + (ty << 2) + i;
        int s = mg >> 6, b = mg & 63;
#pragma unroll
        for (int j = 0; j < 4; j++) {
            int n = n0 + (tx << 2) + j;
            float v = acc[i][j] + b_qkv[EDIM + n];
            if (n < EDIM) {
                int h = n >> 8, d = n & 255;
                g_buf[KT_OFF + (((b << 2) + h) * 256 + d) * 256 + s] = v;   // K: [b,h,d,s]
            } else {
                int n2 = n - EDIM;
                int h = n2 >> 8, d = n2 & 255;
                g_buf[VT_OFF + (((b << 2) + h) * 256 + s) * 256 + d] = v;   // V: [b,h,s,d]
            }
        }
    }
}

// ---------------- A-tile fetch (seg by k>>10; optional 4-slice sum + bias on seg 2) --------
__device__ __forceinline__ float4 loadA(int kk, int a0, int a1, int a2,
                                        int lr, int lk, const float* sumBias) {
    int seg = kk >> 10, kin = kk & 1023;
    int ab = (seg == 0 ? a0 : (seg == 1 ? a1 : a2));
    const float* p = g_buf + ab + lr * 1024 + kin + lk;
    float4 v = __ldcg((const float4*)p);
    if (sumBias && seg == 2) {
#pragma unroll
        for (int sp = 1; sp < 4; sp++) {
            float4 u = __ldcg((const float4*)(p + sp * 65536));
            v.x += u.x; v.y += u.y; v.z += u.z; v.w += u.w;
        }
        v.x += sumBias[kin + lk];     v.y += sumBias[kin + lk + 1];
        v.z += sumBias[kin + lk + 2]; v.w += sumBias[kin + lk + 3];
    }
    return v;
}

// ---------------- per-step GEMM (M=64): k-major W via 4-stage cp.async ----------------
__device__ __noinline__ void gemm64(const float* __restrict__ WT, int N,
                                    int a0, int a1, int a2,
                                    int k0, int Kper, int outOff, int bx, int slice,
                                    float* shA, float* shW, const float* sumBias)
{
    int tid = threadIdx.x;
    int ty = tid >> 4, tx = tid & 15;
    int lr = tid >> 2, lk = (tid & 3) << 2;      // A loader: row lr, k-quarter lk
    int kk = tid >> 4, nq = tid & 15;            // W loader: k-row kk, n-quarter nq
    int n0 = bx << 6;
    int nt = Kper >> 4;

    const float* wsrc = WT + (size_t)(k0 + kk) * N + n0 + (nq << 2);
    float* wdst = shW + kk * 64 + (nq << 2);

    unsigned long long a00=0,a01=0,a10=0,a11=0,a20=0,a21=0,a30=0,a31=0;

    // preamble: W stages 0..2, A(0) -> stage 0, prefetch A(1)
#pragma unroll
    for (int s = 0; s < 3; s++) {
        if (s < nt) cp16(wdst + (s & 3) * WS_STAGE, wsrc + (size_t)(s << 4) * N);
        CP_COMMIT();
    }
    float4 av = loadA(k0, a0, a1, a2, lr, lk, sumBias);
    {
        float* A = shA;
        *(float2*)&A[(lk+0)*132 + lr*2] = make_float2(av.x, av.x);
        *(float2*)&A[(lk+1)*132 + lr*2] = make_float2(av.y, av.y);
        *(float2*)&A[(lk+2)*132 + lr*2] = make_float2(av.z, av.z);
        *(float2*)&A[(lk+3)*132 + lr*2] = make_float2(av.w, av.w);
    }
    if (nt > 1) av = loadA(k0 + 16, a0, a1, a2, lr, lk, sumBias);
    CP_WAIT2();
    __syncthreads();

    for (int t = 0; t < nt; t++) {
        if (t + 3 < nt) cp16(wdst + ((t + 3) & 3) * WS_STAGE, wsrc + (size_t)((t + 3) << 4) * N);
        CP_COMMIT();
        if (t + 1 < nt) {   // stage A(t+1)
            float* A = shA + ((t + 1) & 1) * AD_STAGE;
            *(float2*)&A[(lk+0)*132 + lr*2] = make_float2(av.x, av.x);
            *(float2*)&A[(lk+1)*132 + lr*2] = make_float2(av.y, av.y);
            *(float2*)&A[(lk+2)*132 + lr*2] = make_float2(av.z, av.z);
            *(float2*)&A[(lk+3)*132 + lr*2] = make_float2(av.w, av.w);
        }
        if (t + 2 < nt)     // prefetch A(t+2)
            av = loadA(k0 + ((t + 2) << 4), a0, a1, a2, lr, lk, sumBias);
        const float* A = shA + (t & 1) * AD_STAGE;
        const float* W = shW + (t & 3) * WS_STAGE;
#pragma unroll
        for (int k = 0; k < 16; k++) {
            ulonglong2 aA = *(const ulonglong2*)&A[k*132 + ty*8];
            ulonglong2 aB = *(const ulonglong2*)&A[k*132 + ty*8 + 4];
            ulonglong2 w  = *(const ulonglong2*)&W[k*64 + tx*4];
            fma2(a00, aA.x, w.x); fma2(a01, aA.x, w.y);
            fma2(a10, aA.y, w.x); fma2(a11, aA.y, w.y);
            fma2(a20, aB.x, w.x); fma2(a21, aB.x, w.y);
            fma2(a30, aB.y, w.x); fma2(a31, aB.y, w.y);
        }
        CP_WAIT2();
        __syncthreads();
    }

    float* op = g_buf + outOff + (size_t)slice * 64 * N + n0 + (tx << 2);
    float2 p0, p1;
    p0 = upk2(a00); p1 = upk2(a01); *(float4*)(op + (size_t)((ty<<2)+0)*N) = make_float4(p0.x,p0.y,p1.x,p1.y);
    p0 = upk2(a10); p1 = upk2(a11); *(float4*)(op + (size_t)((ty<<2)+1)*N) = make_float4(p0.x,p0.y,p1.x,p1.y);
    p0 = upk2(a20); p1 = upk2(a21); *(float4*)(op + (size_t)((ty<<2)+2)*N) = make_float4(p0.x,p0.y,p1.x,p1.y);
    p0 = upk2(a30); p1 = upk2(a31); *(float4*)(op + (size_t)((ty<<2)+3)*N) = make_float4(p0.x,p0.y,p1.x,p1.y);
}

// ---------------- attention: one (b,h) per CTA; fp32 K/V; shuffle softmax ----------------
__device__ __noinline__ void attn_dev(const float* __restrict__ b_qkv, float* sh) {
    float* qs   = sh;          // 256
    float* pr   = sh + 256;    // 256
    float* wred = sh + 512;    // 8
    int t = threadIdx.x;
    int lane = t & 31, w = t >> 5;
    int bh = blockIdx.x;              // 0..255
    int b = bh >> 2, h = bh & 3;
    int e = (h << 8) + t;
    float qv = b_qkv[e];
#pragma unroll
    for (int sp = 0; sp < 4; sp++) qv += __ldcg(g_buf + QP_OFF + sp * 65536 + (b << 10) + e);
    qs[t] = qv * 0.0625f;             // fold 1/sqrt(256)
    __syncthreads();

    const float* Kb = g_buf + KT_OFF + bh * 65536;
    float acc = 0.f;
#pragma unroll 16
    for (int d = 0; d < 256; d++) acc += qs[d] * Kb[(d << 8) + t];

    float m = acc;
#pragma unroll
    for (int off = 16; off; off >>= 1) m = fmaxf(m, __shfl_xor_sync(0xffffffffu, m, off));
    if (lane == 0) wred[w] = m;
    __syncthreads();
    float mx = wred[0];
#pragma unroll
    for (int j = 1; j < 8; j++) mx = fmaxf(mx, wred[j]);
    float ex = expf(acc - mx);
    float s = ex;
#pragma unroll
    for (int off = 16; off; off >>= 1) s += __shfl_xor_sync(0xffffffffu, s, off);
    __syncthreads();
    if (lane == 0) wred[w] = s;
    __syncthreads();
    float tot = wred[0];
#pragma unroll
    for (int j = 1; j < 8; j++) tot += wred[j];
    pr[t] = ex * (1.f / tot);
    __syncthreads();

    const float* Vb = g_buf + VT_OFF + bh * 65536;
    float c = 0.f;
#pragma unroll 16
    for (int s2 = 0; s2 < 256; s2++) c += pr[s2] * Vb[(s2 << 8) + t];
    g_buf[ATT_OFF + (b << 10) + e] = c;
}

// ---------------- LSTM cell: sums 7 split-K gate partials + biases ----------------
__device__ __noinline__ void cell_dev(int gOff, const float* __restrict__ bi, const float* __restrict__ bh,
                                      int hOff, int cOff) {
    int idx = blockIdx.x * NTHR + threadIdx.x;    // exactly 65536 = (b,e)
    int b = idx >> 10, e = idx & 1023;
    const float* gb = g_buf + gOff + (size_t)b * 4096;
    float gi = bi[e]        + bh[e];
    float gf = bi[1024 + e] + bh[1024 + e];
    float gg = bi[2048 + e] + bh[2048 + e];
    float go = bi[3072 + e] + bh[3072 + e];
#pragma unroll
    for (int sp = 0; sp < 7; sp++) {
        const float* g = gb + sp * 262144;
        gi += __ldcg(g + e);
        gf += __ldcg(g + 1024 + e);
        gg += __ldcg(g + 2048 + e);
        go += __ldcg(g + 3072 + e);
    }
    float c = __ldcg(g_buf + cOff + idx);
    float cn = sigf(gf) * c + sigf(gi) * tanhf(gg);
    g_buf[cOff + idx] = cn;
    g_buf[hOff + idx] = sigf(go) * tanhf(cn);
}

// ---------------- output head (runs inside phase 1 on CTAs 0..63) ----------------
__device__ __forceinline__ void head_dev(const float* __restrict__ w_out, const float* __restrict__ b_out,
                                         float* __restrict__ out, int t) {
    if (threadIdx.x < 160) {
        int b = blockIdx.x;
        int w = threadIdx.x >> 5, lane = threadIdx.x & 31;
        const float* hb = g_buf + H2_OFF + (b << 10);
        const float* wr = w_out + w * 1024;
        float a = 0.f;
        for (int j = lane; j < 1024; j += 32) a += __ldcg(hb + j) * wr[j];
#pragma unroll
        for (int off = 16; off; off >>= 1) a += __shfl_down_sync(0xffffffffu, a, off);
        if (lane == 0) {
            a += b_out[w];
            if (w >= 2) a = 1.f / (1.f + expf(-a));
            out[((t << 6) + b) * VDIM + w] = a;
        }
    }
}

// ---------------- persistent main kernel ----------------
__global__ void __launch_bounds__(NTHR, 2) main_kernel(
    const float* __restrict__ b_qkv, const float* __restrict__ b_o,
    const float* __restrict__ b_ih1, const float* __restrict__ b_hh1,
    const float* __restrict__ b_ih2, const float* __restrict__ b_hh2,
    const float* __restrict__ w_out, const float* __restrict__ b_out,
    float* __restrict__ out)
{
    __shared__ __align__(16) float sh[SH_FLOATS];
    float* shA = sh;
    float* shW = sh + 2 * AD_STAGE;
    int r = blockIdx.x;
    int grp = r >> 4;

    // zero recurrent state (h1,c1,h2,c2)
    for (int i = r * NTHR + threadIdx.x; i < 4 * BDIM * EDIM; i += NCTA * NTHR)
        g_buf[H1_OFF + i] = 0.f;
    grid_bar(grp);

    const float* QT  = g_buf + QT_OFF;
    const float* OT  = g_buf + OT_OFF;
    const float* G1T = g_buf + G1T_OFF;
    const float* G2T = g_buf + G2T_OFF;

    for (int t = 0; t < SDIM; t++) {
        // ---- P1: {r<64: head(t-1) + q-proj}  {r>=64: gates1 [h2|h1] partials} ----
        if (r < 64) {
            if (t > 0) head_dev(w_out, b_out, out, t - 1);
            gemm64(QT, 1024, H2_OFF, H2_OFF, H2_OFF,
                   (r >> 4) * 256, 256, QP_OFF, r & 15, r >> 4, shA, shW, 0);
        } else {
            int idx = r - 64, bx = idx & 63, byv = idx >> 6;       // byv 0..2
            int k0v  = (byv == 0) ? 0 : (byv == 1 ? 688 : 1376);
            int kpv  = (byv == 2) ? 672 : 688;
            gemm64(G1T, 4096, H2_OFF, H1_OFF, H1_OFF,
                   k0v, kpv, G1_OFF, bx, byv, shA, shW, 0);
        }
        grid_bar(grp);
        // ---- P2: attention (sums 4 q partials + b_q) ----
        attn_dev(b_qkv, sh);
        grid_bar(grp);
        // ---- P3: {r<64: wo partials}  {r>=64: gates2 h2prev partials} ----
        if (r < 64) {
            gemm64(OT, 1024, ATT_OFF, ATT_OFF, ATT_OFF,
                   (r >> 4) * 256, 256, WOP_OFF, r & 15, r >> 4, shA, shW, 0);
        } else {
            int idx = r - 64, bx = idx & 63, byv = idx >> 6;
            int k0v = (byv == 0) ? 1024 : (byv == 1 ? 1376 : 1728);
            int kpv = (byv == 2) ? 320 : 352;
            gemm64(G2T, 4096, H2_OFF, H2_OFF, H2_OFF,
                   k0v, kpv, G2_OFF, bx, byv, shA, shW, 0);
        }
        grid_bar(grp);
        // ---- P4: gates1 ctx part (A = 4 WOP slices + b_o, summed inline) ----
        gemm64(G1T, 4096, H2_OFF, H1_OFF, WOP_OFF,
               2048 + (r & 3) * 256, 256, G1_OFF, r >> 2, 3 + (r & 3), shA, shW, b_o);
        grid_bar(grp);
        // ---- P5: LSTM cell 1 (7 slices) ----
        cell_dev(G1_OFF, b_ih1, b_hh1, H1_OFF, C1_OFF);
        grid_bar(grp);
        // ---- P6: gates2 h1new part ----
        gemm64(G2T, 4096, H1_OFF, H2_OFF, H2_OFF,
               (r & 3) * 256, 256, G2_OFF, r >> 2, 3 + (r & 3), shA, shW, 0);
        grid_bar(grp);
        // ---- P7: LSTM cell 2 (7 slices; writes new h2) ----
        cell_dev(G2_OFF, b_ih2, b_hh2, H2_OFF, C2_OFF);
        grid_bar(grp);
    }
    if (r < 64) head_dev(w_out, b_out, out, SDIM - 1);
}

// ---------------- host ----------------
extern "C" void kernel_launch(void* const* d_in, const int* in_sizes, int n_in,
                              void* d_out, int out_size) {
    const float* cnn    = (const float*)d_in[0];
    const float* w_qkv  = (const float*)d_in[1];
    const float* b_qkv  = (const float*)d_in[2];
    const float* w_o    = (const float*)d_in[3];
    const float* b_o    = (const float*)d_in[4];
    const float* w_ih1  = (const float*)d_in[5];
    const float* w_hh1  = (const float*)d_in[6];
    const float* b_ih1  = (const float*)d_in[7];
    const float* b_hh1  = (const float*)d_in[8];
    const float* w_ih2  = (const float*)d_in[9];
    const float* w_hh2  = (const float*)d_in[10];
    const float* b_ih2  = (const float*)d_in[11];
    const float* b_hh2  = (const float*)d_in[12];
    const float* w_out  = (const float*)d_in[13];
    const float* b_out  = (const float*)d_in[14];
    float* out = (float*)d_out;

    // setup: k-major fp32 weights (1 launch), fp32 K/V (1 launch)
    prep_weights<<<22528, dim3(32, 8)>>>(w_qkv, w_o, w_ih1, w_hh1, w_ih2, w_hh2);
    gemm_kv<<<dim3(32, 256), 256>>>(cnn, w_qkv, b_qkv);

    // entire recurrence in one persistent kernel (256 co-resident CTAs, 2/SM)
    main_kernel<<<NCTA, NTHR>>>(b_qkv, b_o,
                                b_ih1, b_hh1, b_ih2, b_hh2,
                                w_out, b_out, out);
}